// round 10
// baseline (speedup 1.0000x reference)
#include <cuda_runtime.h>
#include <cstdint>

#define NUM_USERS 100000
#define NUM_ITEMS 50000
#define NN 150000          // N_NODES
#define NE 4000000         // N_EDGES
#define H 64
#define BATCH 100000
#define MLPH 32
#define NTILES ((NN + 1023) / 1024)   // 147

#define FUSED_GRID 592     // 4 blocks/SM target, grid-stride
#define WSTRIDE 68         // smem row stride (floats): conflict-free for (g,tig) reads
#define BSTRIDE 132        // global B row stride (floats), [n][k] layout

// ---- scratch (allocation-free: __device__ globals) ----
__device__ __align__(256) float g_xa[NN * H];
__device__ __align__(256) float g_xb[NN * H];
__device__ __align__(256) float g_bhi[3 * 64 * BSTRIDE];
__device__ __align__(256) float g_blo[3 * 64 * BSTRIDE];
__device__ int g_cnt[NN];      // BSS-zeroed at load; re-zeroed by k_scan1 each call
__device__ int g_off[NN + 1];
__device__ int g_cur[NN];
__device__ int g_srcs[NE];
__device__ int g_psum[NTILES];

// ============================================================
// tf32 helpers
// ============================================================
__device__ __forceinline__ uint32_t f2tf32(float f) {
    uint32_t r;
    asm("cvt.rna.tf32.f32 %0, %1;" : "=r"(r) : "f"(f));
    return r;
}
__device__ __forceinline__ void mma_tf32(float c[4],
        uint32_t a0, uint32_t a1, uint32_t a2, uint32_t a3,
        uint32_t b0, uint32_t b1) {
    asm volatile("mma.sync.aligned.m16n8k8.row.col.f32.tf32.tf32.f32 "
        "{%0,%1,%2,%3}, {%4,%5,%6,%7}, {%8,%9}, {%0,%1,%2,%3};"
        : "+f"(c[0]), "+f"(c[1]), "+f"(c[2]), "+f"(c[3])
        : "r"(a0), "r"(a1), "r"(a2), "r"(a3), "r"(b0), "r"(b1));
}

// ============================================================
// 1) setup: concat embeddings + degree count + weight hi/lo split
//    (g_cnt is zero at entry: BSS init on first call, k_scan1 re-zeroes after)
// ============================================================
__global__ void k_setup(const float* __restrict__ ue, const float* __restrict__ ie,
                        const int* __restrict__ dst,
                        const float* __restrict__ Wl, const float* __restrict__ Wr) {
    int i = blockIdx.x * blockDim.x + threadIdx.x;
    const int nu4 = NUM_USERS * H / 4;   // 1,600,000
    const int ni4 = NUM_ITEMS * H / 4;   //   800,000
    float4* xa = (float4*)g_xa;
    if (i < nu4 + ni4) {
        xa[i] = (i < nu4) ? ((const float4*)ue)[i] : ((const float4*)ie)[i - nu4];
    }
    // weight split: 3 layers x (k=128) x (n=64) -> [l][n][k] stride BSTRIDE
    if (i < 3 * 128 * 64) {
        int l = i / (128 * 64);
        int r = i % (128 * 64);
        int k = r >> 6, n = r & 63;
        float v = (k < 64) ? Wl[l * 4096 + k * 64 + n] : Wr[l * 4096 + (k - 64) * 64 + n];
        uint32_t hb = f2tf32(v);
        float hi = __uint_as_float(hb);
        uint32_t lb = f2tf32(v - hi);
        int o = l * 64 * BSTRIDE + n * BSTRIDE + k;
        g_bhi[o] = hi;
        g_blo[o] = __uint_as_float(lb);
    }
    int ei = i * 4;
    if (ei < NE) {
        int4 d = *(const int4*)&dst[ei];
        atomicAdd(&g_cnt[d.x], 1);
        atomicAdd(&g_cnt[d.y], 1);
        atomicAdd(&g_cnt[d.z], 1);
        atomicAdd(&g_cnt[d.w], 1);
    }
}

// ============================================================
// 2) scans (3-phase); scan1 re-zeroes g_cnt for the next call/replay
// ============================================================
__global__ void k_scan1() {
    __shared__ __align__(16) int sdata[1024];
    int tid = threadIdx.x;
    int i = blockIdx.x * 1024 + tid;
    int v = 0;
    if (i < NN) { v = g_cnt[i]; g_cnt[i] = 0; }
    sdata[tid] = v;
    __syncthreads();
    #pragma unroll
    for (int ofs = 1; ofs < 1024; ofs <<= 1) {
        int t = (tid >= ofs) ? sdata[tid - ofs] : 0;
        __syncthreads();
        sdata[tid] += t;
        __syncthreads();
    }
    if (i < NN) g_off[i] = sdata[tid] - v;
    if (tid == 1023) g_psum[blockIdx.x] = sdata[1023];
}

__global__ void k_scan2() {
    __shared__ __align__(16) int sdata[256];
    int tid = threadIdx.x;
    int v = (tid < NTILES) ? g_psum[tid] : 0;
    sdata[tid] = v;
    __syncthreads();
    #pragma unroll
    for (int ofs = 1; ofs < 256; ofs <<= 1) {
        int t = (tid >= ofs) ? sdata[tid - ofs] : 0;
        __syncthreads();
        sdata[tid] += t;
        __syncthreads();
    }
    if (tid < NTILES) g_psum[tid] = sdata[tid] - v;
}

__global__ void k_scan3() {
    int i = blockIdx.x * blockDim.x + threadIdx.x;
    if (i < NN) {
        int o = g_off[i] + g_psum[blockIdx.x >> 2];
        g_off[i] = o;
        g_cur[i] = o;
    }
    if (i == 0) g_off[NN] = NE;
}

// ============================================================
// 3) bucket edges by dst — 4 edges per thread
// ============================================================
__global__ void k_bucket(const int* __restrict__ src, const int* __restrict__ dst) {
    int i = (blockIdx.x * blockDim.x + threadIdx.x) * 4;
    if (i < NE) {
        int4 d = *(const int4*)&dst[i];
        int4 s = *(const int4*)&src[i];
        int p0 = atomicAdd(&g_cur[d.x], 1);
        int p1 = atomicAdd(&g_cur[d.y], 1);
        int p2 = atomicAdd(&g_cur[d.z], 1);
        int p3 = atomicAdd(&g_cur[d.w], 1);
        g_srcs[p0] = s.x;
        g_srcs[p1] = s.y;
        g_srcs[p2] = s.z;
        g_srcs[p3] = s.w;
    }
}

// ============================================================
// 4) FUSED layer: warp owns a 16x64 output tile.
//    Phase A: gather 16 nodes' means into smem staging (stride 68).
//    Phase B: 3xTF32 MMA; mean operand from smem, xin + weights from L1.
//    xout = relu(mean @ Wl + xin @ Wr + b)
// ============================================================
__global__ __launch_bounds__(256) void k_fused(
        const float* __restrict__ xin, float* __restrict__ xout,
        const float* __restrict__ bhi, const float* __restrict__ blo,
        const float* __restrict__ bvec) {
    __shared__ __align__(16) float sr[8][16 * WSTRIDE];   // 34816 B

    int tid = threadIdx.x;
    int wid = tid >> 5, lane = tid & 31;
    int h = lane >> 4, l4 = lane & 15;        // gather mapping
    int g = lane >> 2, tig = lane & 3;        // mma fragment mapping
    const float4* x4 = (const float4*)xin;
    float* srw = sr[wid];

    float2 bias[8];
    #pragma unroll
    for (int n0 = 0; n0 < 8; n0++)
        bias[n0] = *(const float2*)&bvec[n0 * 8 + 2 * tig];

    int nwarp = gridDim.x * 8;
    for (int wt = blockIdx.x * 8 + wid; wt < NN / 16; wt += nwarp) {
        int r0 = wt * 16;

        // ---- phase A: gather means for rows r0..r0+15 ----
        #pragma unroll 1
        for (int j = 0; j < 16; j++) {
            int n = r0 + j;
            int s = g_off[n], e = g_off[n + 1];
            float4 a0 = make_float4(0.f, 0.f, 0.f, 0.f);
            float4 a1 = make_float4(0.f, 0.f, 0.f, 0.f);
            float4 a2 = make_float4(0.f, 0.f, 0.f, 0.f);
            float4 a3 = make_float4(0.f, 0.f, 0.f, 0.f);
            int i = s;
            for (; i + 7 < e; i += 8) {
                int n0 = __ldg(&g_srcs[i     + h]);
                int n1 = __ldg(&g_srcs[i + 2 + h]);
                int n2 = __ldg(&g_srcs[i + 4 + h]);
                int n3 = __ldg(&g_srcs[i + 6 + h]);
                float4 v0 = __ldg(&x4[n0 * 16 + l4]);
                float4 v1 = __ldg(&x4[n1 * 16 + l4]);
                float4 v2 = __ldg(&x4[n2 * 16 + l4]);
                float4 v3 = __ldg(&x4[n3 * 16 + l4]);
                a0.x += v0.x; a0.y += v0.y; a0.z += v0.z; a0.w += v0.w;
                a1.x += v1.x; a1.y += v1.y; a1.z += v1.z; a1.w += v1.w;
                a2.x += v2.x; a2.y += v2.y; a2.z += v2.z; a2.w += v2.w;
                a3.x += v3.x; a3.y += v3.y; a3.z += v3.z; a3.w += v3.w;
            }
            for (; i + 1 < e; i += 2) {
                int nn = __ldg(&g_srcs[i + h]);
                float4 v = __ldg(&x4[nn * 16 + l4]);
                a0.x += v.x; a0.y += v.y; a0.z += v.z; a0.w += v.w;
            }
            if (i < e && h == 0) {
                int nn = __ldg(&g_srcs[i]);
                float4 v = __ldg(&x4[nn * 16 + l4]);
                a0.x += v.x; a0.y += v.y; a0.z += v.z; a0.w += v.w;
            }
            float4 acc;
            acc.x = (a0.x + a1.x) + (a2.x + a3.x);
            acc.y = (a0.y + a1.y) + (a2.y + a3.y);
            acc.z = (a0.z + a1.z) + (a2.z + a3.z);
            acc.w = (a0.w + a1.w) + (a2.w + a3.w);
            acc.x += __shfl_xor_sync(0xffffffffu, acc.x, 16);
            acc.y += __shfl_xor_sync(0xffffffffu, acc.y, 16);
            acc.z += __shfl_xor_sync(0xffffffffu, acc.z, 16);
            acc.w += __shfl_xor_sync(0xffffffffu, acc.w, 16);
            int c = e - s;
            float inv = 1.0f / (float)(c > 1 ? c : 1);
            if (h == 0) {
                float4 m = make_float4(acc.x * inv, acc.y * inv, acc.z * inv, acc.w * inv);
                *(float4*)&srw[j * WSTRIDE + l4 * 4] = m;
            }
        }
        __syncwarp();

        // ---- phase B: MMA ----
        float c[8][4];
        #pragma unroll
        for (int n0 = 0; n0 < 8; n0++)
            c[n0][0] = c[n0][1] = c[n0][2] = c[n0][3] = 0.f;

        // op 0: mean (from smem), B rows k = 0..63
        #pragma unroll
        for (int ks = 0; ks < 8; ks++) {
            int col = ks * 8 + tig;
            float f0 = srw[g * WSTRIDE + col];
            float f1 = srw[(g + 8) * WSTRIDE + col];
            float f2 = srw[g * WSTRIDE + col + 4];
            float f3 = srw[(g + 8) * WSTRIDE + col + 4];
            uint32_t ah0 = f2tf32(f0), ah1 = f2tf32(f1);
            uint32_t ah2 = f2tf32(f2), ah3 = f2tf32(f3);
            uint32_t al0 = f2tf32(f0 - __uint_as_float(ah0));
            uint32_t al1 = f2tf32(f1 - __uint_as_float(ah1));
            uint32_t al2 = f2tf32(f2 - __uint_as_float(ah2));
            uint32_t al3 = f2tf32(f3 - __uint_as_float(ah3));
            int kk = ks * 8;
            #pragma unroll
            for (int n0 = 0; n0 < 8; n0++) {
                int nrow = (n0 * 8 + g) * BSTRIDE + kk + tig;
                uint32_t bh0 = __float_as_uint(__ldg(&bhi[nrow]));
                uint32_t bh1 = __float_as_uint(__ldg(&bhi[nrow + 4]));
                uint32_t bl0 = __float_as_uint(__ldg(&blo[nrow]));
                uint32_t bl1 = __float_as_uint(__ldg(&blo[nrow + 4]));
                mma_tf32(c[n0], ah0, ah1, ah2, ah3, bh0, bh1);
                mma_tf32(c[n0], ah0, ah1, ah2, ah3, bl0, bl1);
                mma_tf32(c[n0], al0, al1, al2, al3, bh0, bh1);
            }
        }
        // op 1: xin (from global/L1), B rows k = 64..127
        #pragma unroll
        for (int ks = 0; ks < 8; ks++) {
            int col = ks * 8 + tig;
            float f0 = __ldg(&xin[(r0 + g) * 64 + col]);
            float f1 = __ldg(&xin[(r0 + g + 8) * 64 + col]);
            float f2 = __ldg(&xin[(r0 + g) * 64 + col + 4]);
            float f3 = __ldg(&xin[(r0 + g + 8) * 64 + col + 4]);
            uint32_t ah0 = f2tf32(f0), ah1 = f2tf32(f1);
            uint32_t ah2 = f2tf32(f2), ah3 = f2tf32(f3);
            uint32_t al0 = f2tf32(f0 - __uint_as_float(ah0));
            uint32_t al1 = f2tf32(f1 - __uint_as_float(ah1));
            uint32_t al2 = f2tf32(f2 - __uint_as_float(ah2));
            uint32_t al3 = f2tf32(f3 - __uint_as_float(ah3));
            int kk = 64 + ks * 8;
            #pragma unroll
            for (int n0 = 0; n0 < 8; n0++) {
                int nrow = (n0 * 8 + g) * BSTRIDE + kk + tig;
                uint32_t bh0 = __float_as_uint(__ldg(&bhi[nrow]));
                uint32_t bh1 = __float_as_uint(__ldg(&bhi[nrow + 4]));
                uint32_t bl0 = __float_as_uint(__ldg(&blo[nrow]));
                uint32_t bl1 = __float_as_uint(__ldg(&blo[nrow + 4]));
                mma_tf32(c[n0], ah0, ah1, ah2, ah3, bh0, bh1);
                mma_tf32(c[n0], ah0, ah1, ah2, ah3, bl0, bl1);
                mma_tf32(c[n0], al0, al1, al2, al3, bh0, bh1);
            }
        }

        // epilogue: bias + relu + store
        #pragma unroll
        for (int n0 = 0; n0 < 8; n0++) {
            float2 o01, o23;
            o01.x = fmaxf(c[n0][0] + bias[n0].x, 0.f);
            o01.y = fmaxf(c[n0][1] + bias[n0].y, 0.f);
            o23.x = fmaxf(c[n0][2] + bias[n0].x, 0.f);
            o23.y = fmaxf(c[n0][3] + bias[n0].y, 0.f);
            int ccol = n0 * 8 + 2 * tig;
            *(float2*)&xout[(r0 + g) * 64 + ccol] = o01;
            *(float2*)&xout[(r0 + g + 8) * 64 + ccol] = o23;
        }
        __syncwarp();
    }
}

// ============================================================
// 5) final MLP: warp per pair
// ============================================================
__global__ void k_mlp(const float* __restrict__ x,
                      const int* __restrict__ uid, const int* __restrict__ iid,
                      const float* __restrict__ W1, const float* __restrict__ b1,
                      const float* __restrict__ W2, const float* __restrict__ b2,
                      float* __restrict__ out) {
    __shared__ __align__(16) float sW1[2 * H * MLPH];
    __shared__ __align__(16) float sW2[MLPH];
    __shared__ __align__(16) float sb1[MLPH];
    __shared__ float sb2;
    __shared__ __align__(16) float spair[8][2 * H];

    int tid = threadIdx.x;
    for (int i = tid; i < 2 * H * MLPH; i += 256) sW1[i] = W1[i];
    if (tid < MLPH) { sW2[tid] = W2[tid]; sb1[tid] = b1[tid]; }
    if (tid == 0) sb2 = b2[0];
    __syncthreads();

    int wid = tid >> 5, lane = tid & 31;
    for (int i = blockIdx.x * 8 + wid; i < BATCH; i += gridDim.x * 8) {
        int u = __ldg(&uid[i]);
        int it = __ldg(&iid[i]) + NUM_USERS;
        const float4* ur = (const float4*)(x + (size_t)u * H);
        const float4* ir = (const float4*)(x + (size_t)it * H);
        if (lane < 16) {
            *(float4*)&spair[wid][lane * 4] = __ldg(&ur[lane]);
        } else {
            *(float4*)&spair[wid][64 + (lane - 16) * 4] = __ldg(&ir[lane - 16]);
        }
        __syncwarp();
        float h = sb1[lane];
        #pragma unroll 16
        for (int k = 0; k < 2 * H; k++) {
            h += spair[wid][k] * sW1[k * MLPH + lane];
        }
        h = fmaxf(h, 0.f);
        float r = h * sW2[lane];
        #pragma unroll
        for (int o = 16; o; o >>= 1) r += __shfl_xor_sync(0xffffffffu, r, o);
        if (lane == 0) out[i] = fminf(fmaxf(r + sb2, 1.0f), 5.0f);
        __syncwarp();
    }
}

// ============================================================
// launch
// ============================================================
extern "C" void kernel_launch(void* const* d_in, const int* in_sizes, int n_in,
                              void* d_out, int out_size) {
    (void)in_sizes; (void)n_in; (void)out_size;
    const int*   edge = (const int*)d_in[0];
    const int*   src  = edge;
    const int*   dst  = edge + NE;
    const int*   uid  = (const int*)d_in[1];
    const int*   iid  = (const int*)d_in[2];
    const float* ue   = (const float*)d_in[3];
    const float* ie   = (const float*)d_in[4];
    const float* Wl   = (const float*)d_in[5];
    const float* bl   = (const float*)d_in[6];
    const float* Wr   = (const float*)d_in[7];
    const float* W1   = (const float*)d_in[8];
    const float* b1   = (const float*)d_in[9];
    const float* W2   = (const float*)d_in[10];
    const float* b2   = (const float*)d_in[11];
    float* out = (float*)d_out;

    float *xa, *xb, *bhi, *blo;
    cudaGetSymbolAddress((void**)&xa, g_xa);
    cudaGetSymbolAddress((void**)&xb, g_xb);
    cudaGetSymbolAddress((void**)&bhi, g_bhi);
    cudaGetSymbolAddress((void**)&blo, g_blo);

    // 1: setup (concat + count + weight split)   [g_cnt zero: BSS / scan1 restore]
    k_setup<<<(2400000 + 255) / 256, 256>>>(ue, ie, dst, Wl, Wr);
    // 2-4: scans
    k_scan1<<<NTILES, 1024>>>();
    k_scan2<<<1, 256>>>();
    k_scan3<<<NTILES * 4, 256>>>();
    // 5: bucket
    k_bucket<<<(NE / 4 + 255) / 256, 256>>>(src, dst);

    // 6-8: fused layers (launch #6 = layer 0 -> ncu capture slot)
    float* cur = xa;
    float* nxt = xb;
    for (int l = 0; l < 3; l++) {
        k_fused<<<FUSED_GRID, 256>>>(cur, nxt,
                                     bhi + l * 64 * BSTRIDE, blo + l * 64 * BSTRIDE,
                                     bl + l * H);
        float* t = cur; cur = nxt; nxt = t;
    }

    k_mlp<<<2048, 256>>>(cur, uid, iid, W1, b1, W2, b2, out);
}

// round 11
// speedup vs baseline: 1.5609x; 1.5609x over previous
#include <cuda_runtime.h>
#include <cstdint>

#define NUM_USERS 100000
#define NUM_ITEMS 50000
#define NN 150000          // N_NODES
#define NE 4000000         // N_EDGES
#define H 64
#define BATCH 100000
#define MLPH 32
#define NTILES ((NN + 1023) / 1024)   // 147

#define GEMM_GRID 444
#define GEMM_SMEM (2 * 64 * 132 * 4)   // 67584 B: Bhi + Blo, padded rows

// ---- scratch (allocation-free: __device__ globals) ----
__device__ __align__(256) float g_xa[NN * H];
__device__ __align__(256) float g_xb[NN * H];
__device__ __align__(256) float g_mean[NN * H];
__device__ int g_cnt[NN];      // zero at load (BSS); k_scan1 re-zeroes after reading
__device__ int g_off[NN + 1];
__device__ int g_cur[NN];
__device__ int g_srcs[NE];
__device__ int g_psum[NTILES];

// ============================================================
// tf32 helpers
// ============================================================
__device__ __forceinline__ uint32_t f2tf32(float f) {
    uint32_t r;
    asm("cvt.rna.tf32.f32 %0, %1;" : "=r"(r) : "f"(f));
    return r;
}
__device__ __forceinline__ void mma_tf32(float c[4],
        uint32_t a0, uint32_t a1, uint32_t a2, uint32_t a3,
        uint32_t b0, uint32_t b1) {
    asm volatile("mma.sync.aligned.m16n8k8.row.col.f32.tf32.tf32.f32 "
        "{%0,%1,%2,%3}, {%4,%5,%6,%7}, {%8,%9}, {%0,%1,%2,%3};"
        : "+f"(c[0]), "+f"(c[1]), "+f"(c[2]), "+f"(c[3])
        : "r"(a0), "r"(a1), "r"(a2), "r"(a3), "r"(b0), "r"(b1));
}

// ============================================================
// 1) concat embeddings into g_xa (runs on side stream, overlapped with CSR build)
// ============================================================
__global__ void k_concat(const float* __restrict__ ue, const float* __restrict__ ie) {
    int i = blockIdx.x * blockDim.x + threadIdx.x;
    const int nu4 = NUM_USERS * H / 4;   // 1,600,000
    const int ni4 = NUM_ITEMS * H / 4;   //   800,000
    float4* xa = (float4*)g_xa;
    if (i < nu4) {
        xa[i] = ((const float4*)ue)[i];
    } else if (i < nu4 + ni4) {
        xa[i] = ((const float4*)ie)[i - nu4];
    }
}

// ============================================================
// 2) degree count — 4 edges per thread (g_cnt zero at entry)
// ============================================================
__global__ void k_count(const int* __restrict__ dst) {
    int i = (blockIdx.x * blockDim.x + threadIdx.x) * 4;
    if (i < NE) {
        int4 d = *(const int4*)&dst[i];
        atomicAdd(&g_cnt[d.x], 1);
        atomicAdd(&g_cnt[d.y], 1);
        atomicAdd(&g_cnt[d.z], 1);
        atomicAdd(&g_cnt[d.w], 1);
    }
}

// ============================================================
// 3) scans (3-phase); scan1 re-zeroes g_cnt for the next call/replay
// ============================================================
__global__ void k_scan1() {
    __shared__ __align__(16) int sdata[1024];
    int tid = threadIdx.x;
    int i = blockIdx.x * 1024 + tid;
    int v = 0;
    if (i < NN) { v = g_cnt[i]; g_cnt[i] = 0; }
    sdata[tid] = v;
    __syncthreads();
    #pragma unroll
    for (int ofs = 1; ofs < 1024; ofs <<= 1) {
        int t = (tid >= ofs) ? sdata[tid - ofs] : 0;
        __syncthreads();
        sdata[tid] += t;
        __syncthreads();
    }
    if (i < NN) g_off[i] = sdata[tid] - v;
    if (tid == 1023) g_psum[blockIdx.x] = sdata[1023];
}

__global__ void k_scan2() {
    __shared__ __align__(16) int sdata[256];
    int tid = threadIdx.x;
    int v = (tid < NTILES) ? g_psum[tid] : 0;
    sdata[tid] = v;
    __syncthreads();
    #pragma unroll
    for (int ofs = 1; ofs < 256; ofs <<= 1) {
        int t = (tid >= ofs) ? sdata[tid - ofs] : 0;
        __syncthreads();
        sdata[tid] += t;
        __syncthreads();
    }
    if (tid < NTILES) g_psum[tid] = sdata[tid] - v;
}

__global__ void k_scan3() {
    int i = blockIdx.x * blockDim.x + threadIdx.x;
    if (i < NN) {
        int o = g_off[i] + g_psum[blockIdx.x >> 2];
        g_off[i] = o;
        g_cur[i] = o;
    }
    if (i == 0) g_off[NN] = NE;
}

// ============================================================
// 4) bucket edges by dst — 4 edges per thread
// ============================================================
__global__ void k_bucket(const int* __restrict__ src, const int* __restrict__ dst) {
    int i = (blockIdx.x * blockDim.x + threadIdx.x) * 4;
    if (i < NE) {
        int4 d = *(const int4*)&dst[i];
        int4 s = *(const int4*)&src[i];
        int p0 = atomicAdd(&g_cur[d.x], 1);
        int p1 = atomicAdd(&g_cur[d.y], 1);
        int p2 = atomicAdd(&g_cur[d.z], 1);
        int p3 = atomicAdd(&g_cur[d.w], 1);
        g_srcs[p0] = s.x;
        g_srcs[p1] = s.y;
        g_srcs[p2] = s.z;
        g_srcs[p3] = s.w;
    }
}

// ============================================================
// 5) mean aggregation: warp per node, float2 lanes, 4-deep unroll;
//    row loads via __ldcg (no L1 reuse in the 38MB random table)
// ============================================================
__global__ void k_agg(const float* __restrict__ x) {
    int w = (blockIdx.x * blockDim.x + threadIdx.x) >> 5;
    if (w >= NN) return;
    int lane = threadIdx.x & 31;
    const float2* x2p = (const float2*)x;
    int s = g_off[w], e = g_off[w + 1];
    float2 a0 = make_float2(0.f, 0.f), a1 = make_float2(0.f, 0.f);
    float2 a2 = make_float2(0.f, 0.f), a3 = make_float2(0.f, 0.f);
    int i = s;
    for (; i + 3 < e; i += 4) {
        int s0 = __ldg(&g_srcs[i]);
        int s1 = __ldg(&g_srcs[i + 1]);
        int s2 = __ldg(&g_srcs[i + 2]);
        int s3 = __ldg(&g_srcs[i + 3]);
        float2 v0 = __ldcg(&x2p[s0 * 32 + lane]);
        float2 v1 = __ldcg(&x2p[s1 * 32 + lane]);
        float2 v2 = __ldcg(&x2p[s2 * 32 + lane]);
        float2 v3 = __ldcg(&x2p[s3 * 32 + lane]);
        a0.x += v0.x; a0.y += v0.y;
        a1.x += v1.x; a1.y += v1.y;
        a2.x += v2.x; a2.y += v2.y;
        a3.x += v3.x; a3.y += v3.y;
    }
    for (; i < e; i++) {
        int sn = __ldg(&g_srcs[i]);
        float2 v = __ldcg(&x2p[sn * 32 + lane]);
        a0.x += v.x; a0.y += v.y;
    }
    int c = e - s;
    float inv = 1.0f / (float)(c > 1 ? c : 1);
    float2 m;
    m.x = ((a0.x + a1.x) + (a2.x + a3.x)) * inv;
    m.y = ((a0.y + a1.y) + (a2.y + a3.y)) * inv;
    ((float2*)g_mean)[w * 32 + lane] = m;
}

// ============================================================
// 6) tensor-core layer GEMM (3xTF32):
//    xout = relu(mean @ Wl + xin @ Wr + b)  — weights staged in smem
// ============================================================
__global__ __launch_bounds__(256) void k_gemm(
        const float* __restrict__ xin, float* __restrict__ xout,
        const float* __restrict__ Wl, const float* __restrict__ bl,
        const float* __restrict__ Wr) {
    extern __shared__ float smem[];
    float* sBhi = smem;              // [n=64][k=128] stride 132
    float* sBlo = smem + 64 * 132;

    int tid = threadIdx.x;
    for (int idx = tid; idx < 64 * 128; idx += 256) {
        int k = idx >> 6;
        int n = idx & 63;
        float v = (k < 64) ? Wl[k * 64 + n] : Wr[(k - 64) * 64 + n];
        uint32_t hb = f2tf32(v);
        float hi = __uint_as_float(hb);
        uint32_t lb = f2tf32(v - hi);
        sBhi[n * 132 + k] = __uint_as_float(hb);
        sBlo[n * 132 + k] = __uint_as_float(lb);
    }
    __syncthreads();

    int wid = tid >> 5, lane = tid & 31;
    int g = lane >> 2;
    int tig = lane & 3;

    float2 bias[8];
    #pragma unroll
    for (int n0 = 0; n0 < 8; n0++)
        bias[n0] = *(const float2*)&bl[n0 * 8 + 2 * tig];

    const float* Aops[2] = { g_mean, xin };
    int nwarp = gridDim.x * 8;

    for (int wt = blockIdx.x * 8 + wid; wt < NN / 16; wt += nwarp) {
        int r0 = wt * 16;
        float c[8][4];
        #pragma unroll
        for (int n0 = 0; n0 < 8; n0++)
            c[n0][0] = c[n0][1] = c[n0][2] = c[n0][3] = 0.f;

        #pragma unroll
        for (int op = 0; op < 2; op++) {
            const float* A = Aops[op];
            int kb = op * 64;
            #pragma unroll
            for (int ks = 0; ks < 8; ks++) {
                int col = ks * 8 + tig;
                float f0 = __ldg(&A[(r0 + g) * 64 + col]);
                float f1 = __ldg(&A[(r0 + g + 8) * 64 + col]);
                float f2 = __ldg(&A[(r0 + g) * 64 + col + 4]);
                float f3 = __ldg(&A[(r0 + g + 8) * 64 + col + 4]);
                uint32_t ah0 = f2tf32(f0), ah1 = f2tf32(f1);
                uint32_t ah2 = f2tf32(f2), ah3 = f2tf32(f3);
                uint32_t al0 = f2tf32(f0 - __uint_as_float(ah0));
                uint32_t al1 = f2tf32(f1 - __uint_as_float(ah1));
                uint32_t al2 = f2tf32(f2 - __uint_as_float(ah2));
                uint32_t al3 = f2tf32(f3 - __uint_as_float(ah3));
                int kk = kb + ks * 8;
                #pragma unroll
                for (int n0 = 0; n0 < 8; n0++) {
                    int nrow = (n0 * 8 + g) * 132 + kk + tig;
                    uint32_t bh0 = __float_as_uint(sBhi[nrow]);
                    uint32_t bh1 = __float_as_uint(sBhi[nrow + 4]);
                    uint32_t bl0 = __float_as_uint(sBlo[nrow]);
                    uint32_t bl1 = __float_as_uint(sBlo[nrow + 4]);
                    mma_tf32(c[n0], ah0, ah1, ah2, ah3, bh0, bh1);
                    mma_tf32(c[n0], ah0, ah1, ah2, ah3, bl0, bl1);
                    mma_tf32(c[n0], al0, al1, al2, al3, bh0, bh1);
                }
            }
        }

        #pragma unroll
        for (int n0 = 0; n0 < 8; n0++) {
            float2 o01, o23;
            o01.x = fmaxf(c[n0][0] + bias[n0].x, 0.f);
            o01.y = fmaxf(c[n0][1] + bias[n0].y, 0.f);
            o23.x = fmaxf(c[n0][2] + bias[n0].x, 0.f);
            o23.y = fmaxf(c[n0][3] + bias[n0].y, 0.f);
            int ccol = n0 * 8 + 2 * tig;
            *(float2*)&xout[(r0 + g) * 64 + ccol] = o01;
            *(float2*)&xout[(r0 + g + 8) * 64 + ccol] = o23;
        }
    }
}

// ============================================================
// 7) final MLP: warp per pair
// ============================================================
__global__ void k_mlp(const float* __restrict__ x,
                      const int* __restrict__ uid, const int* __restrict__ iid,
                      const float* __restrict__ W1, const float* __restrict__ b1,
                      const float* __restrict__ W2, const float* __restrict__ b2,
                      float* __restrict__ out) {
    __shared__ __align__(16) float sW1[2 * H * MLPH];
    __shared__ __align__(16) float sW2[MLPH];
    __shared__ __align__(16) float sb1[MLPH];
    __shared__ float sb2;
    __shared__ __align__(16) float spair[8][2 * H];

    int tid = threadIdx.x;
    for (int i = tid; i < 2 * H * MLPH; i += 256) sW1[i] = W1[i];
    if (tid < MLPH) { sW2[tid] = W2[tid]; sb1[tid] = b1[tid]; }
    if (tid == 0) sb2 = b2[0];
    __syncthreads();

    int wid = tid >> 5, lane = tid & 31;
    for (int i = blockIdx.x * 8 + wid; i < BATCH; i += gridDim.x * 8) {
        int u = __ldg(&uid[i]);
        int it = __ldg(&iid[i]) + NUM_USERS;
        const float4* ur = (const float4*)(x + (size_t)u * H);
        const float4* ir = (const float4*)(x + (size_t)it * H);
        if (lane < 16) {
            *(float4*)&spair[wid][lane * 4] = __ldg(&ur[lane]);
        } else {
            *(float4*)&spair[wid][64 + (lane - 16) * 4] = __ldg(&ir[lane - 16]);
        }
        __syncwarp();
        float h = sb1[lane];
        #pragma unroll 16
        for (int k = 0; k < 2 * H; k++) {
            h += spair[wid][k] * sW1[k * MLPH + lane];
        }
        h = fmaxf(h, 0.f);
        float r = h * sW2[lane];
        #pragma unroll
        for (int o = 16; o; o >>= 1) r += __shfl_xor_sync(0xffffffffu, r, o);
        if (lane == 0) out[i] = fminf(fmaxf(r + sb2, 1.0f), 5.0f);
        __syncwarp();
    }
}

// ============================================================
// launch — concat overlapped with CSR build via fork/join streams
// ============================================================
extern "C" void kernel_launch(void* const* d_in, const int* in_sizes, int n_in,
                              void* d_out, int out_size) {
    (void)in_sizes; (void)n_in; (void)out_size;
    const int*   edge = (const int*)d_in[0];
    const int*   src  = edge;
    const int*   dst  = edge + NE;
    const int*   uid  = (const int*)d_in[1];
    const int*   iid  = (const int*)d_in[2];
    const float* ue   = (const float*)d_in[3];
    const float* ie   = (const float*)d_in[4];
    const float* Wl   = (const float*)d_in[5];
    const float* bl   = (const float*)d_in[6];
    const float* Wr   = (const float*)d_in[7];
    const float* W1   = (const float*)d_in[8];
    const float* b1   = (const float*)d_in[9];
    const float* W2   = (const float*)d_in[10];
    const float* b2   = (const float*)d_in[11];
    float* out = (float*)d_out;

    float *xa, *xb;
    cudaGetSymbolAddress((void**)&xa, g_xa);
    cudaGetSymbolAddress((void**)&xb, g_xb);

    cudaFuncSetAttribute(k_gemm, cudaFuncAttributeMaxDynamicSharedMemorySize, GEMM_SMEM);

    // side stream + fork/join events (created per call; kernel_launch only runs
    // a handful of times — graph replays never re-execute host code)
    cudaStream_t s1;
    cudaStreamCreateWithFlags(&s1, cudaStreamNonBlocking);
    cudaEvent_t e0, e1;
    cudaEventCreateWithFlags(&e0, cudaEventDisableTiming);
    cudaEventCreateWithFlags(&e1, cudaEventDisableTiming);

    // fork: concat on s1, CSR chain on stream 0
    cudaEventRecord(e0, 0);
    cudaStreamWaitEvent(s1, e0, 0);
    k_concat<<<(2400000 + 255) / 256, 256, 0, s1>>>(ue, ie);

    k_count<<<(NE / 4 + 255) / 256, 256>>>(dst);
    k_scan1<<<NTILES, 1024>>>();
    k_scan2<<<1, 256>>>();
    k_scan3<<<NTILES * 4, 256>>>();
    k_bucket<<<(NE / 4 + 255) / 256, 256>>>(src, dst);

    // join: layer 0 needs g_xa
    cudaEventRecord(e1, s1);
    cudaStreamWaitEvent(0, e1, 0);

    float* cur = xa;
    float* nxt = xb;
    for (int l = 0; l < 3; l++) {
        k_agg<<<(NN * 32 + 255) / 256, 256>>>(cur);
        k_gemm<<<GEMM_GRID, 256, GEMM_SMEM>>>(cur, nxt, Wl + l * H * H, bl + l * H, Wr + l * H * H);
        float* t = cur; cur = nxt; nxt = t;
    }

    k_mlp<<<2048, 256>>>(cur, uid, iid, W1, b1, W2, b2, out);
}